// round 10
// baseline (speedup 1.0000x reference)
#include <cuda_runtime.h>
#include <cstdint>

#define BATCH 32
#define CH    64
#define OCH   64
#define HW    128
#define NPIX  16384
#define CONDN 16
#define KK    9

typedef unsigned long long ull;

// ---------------- scratch (device globals; no allocation allowed) -------------
__device__ float g_S[BATCH * CH * KK];        // strided sums  [b][c][i*3+j]
__device__ float g_dw[BATCH * CH * KK];       // depthwise weights
__device__ float g_pw[BATCH * CH * OCH];      // pointwise, stored [b][c][o]
__device__ float g_db[BATCH * OCH];           // dynamic bias
__device__ float g_part[2048 * 64];           // per-block (32ch x {s,q}) partials
__device__ float g_scale[OCH];
__device__ float g_shift[OCH];

// =============================================================================
// K1: strided partial sums S[b,c,i,j] = sum_{p,q=0..62} x[b,c,2p+i,2q+j]
// =============================================================================
__global__ void k_ssum(const float* __restrict__ x) {
    int bc = blockIdx.x;                       // b*64 + c
    const float* xp = x + (size_t)bc * NPIX;
    int tid = threadIdx.x;                     // 256
    int s = tid & 127;
    int rbase = tid >> 7;

    float a[9];
#pragma unroll
    for (int m = 0; m < 9; m++) a[m] = 0.f;

    bool se = (s & 1) == 0;
    bool j0 = se && (s <= 124);
    bool j1 = (!se) && (s <= 125);
    bool j2 = se && (s >= 2);

    for (int k = 0; k < 64; k++) {
        int r = rbase + 2 * k;
        float v = xp[r * HW + s];
        bool re = (r & 1) == 0;
        bool i0 = re && (r <= 124);
        bool i1 = (!re) && (r <= 125);
        bool i2 = re && (r >= 2);
        if (i0) { if (j0) a[0] += v; if (j1) a[1] += v; if (j2) a[2] += v; }
        if (i1) { if (j0) a[3] += v; if (j1) a[4] += v; if (j2) a[5] += v; }
        if (i2) { if (j0) a[6] += v; if (j1) a[7] += v; if (j2) a[8] += v; }
    }

#pragma unroll
    for (int m = 0; m < 9; m++)
#pragma unroll
        for (int off = 16; off > 0; off >>= 1)
            a[m] += __shfl_xor_sync(0xffffffffu, a[m], off);

    __shared__ float red[8][9];
    int lane = tid & 31, w = tid >> 5;
    if (lane == 0) {
#pragma unroll
        for (int m = 0; m < 9; m++) red[w][m] = a[m];
    }
    __syncthreads();
    if (tid < 9) {
        float t = 0.f;
#pragma unroll
        for (int w2 = 0; w2 < 8; w2++) t += red[w2][tid];
        g_S[bc * 9 + tid] = t;
    }
}

// =============================================================================
// K2: conditioning network + dynamic weight generators (one block per sample)
// =============================================================================
__global__ void k_cond(const float* __restrict__ cg_w1, const float* __restrict__ cg_b1,
                       const float* __restrict__ cg_w2, const float* __restrict__ cg_b2,
                       const float* __restrict__ wg_w,  const float* __restrict__ wg_b,
                       const float* __restrict__ pg_w,  const float* __restrict__ pg_b,
                       const float* __restrict__ bg_w,  const float* __restrict__ bg_b) {
    int b = blockIdx.x;
    int tid = threadIdx.x;   // 128
    __shared__ float Ssh[CH * KK];
    __shared__ float c1[CONDN];
    __shared__ float c2[CONDN];

    for (int i = tid; i < CH * KK; i += 128) Ssh[i] = g_S[b * (CH * KK) + i];
    __syncthreads();

    if (tid < CONDN) {
        float m = 0.f;
        const float* w = cg_w1 + tid * (CH * KK);
        for (int i = 0; i < CH * KK; i++) m += w[i] * Ssh[i];
        m = m * (1.0f / 3969.0f) + cg_b1[tid];
        c1[tid] = fmaxf(m, 0.f);
    }
    __syncthreads();
    if (tid < CONDN) {
        float m = cg_b2[tid];
#pragma unroll
        for (int k = 0; k < CONDN; k++) m += cg_w2[tid * CONDN + k] * c1[k];
        c2[tid] = fmaxf(m, 0.f);
    }
    __syncthreads();

    for (int n = tid; n < CH * KK; n += 128) {
        float m = wg_b[n];
        const float* w = wg_w + n * CONDN;
#pragma unroll
        for (int k = 0; k < CONDN; k++) m += w[k] * c2[k];
        g_dw[b * (CH * KK) + n] = fmaxf(m, 0.f);
    }
    for (int n = tid; n < OCH * CH; n += 128) {
        float m = pg_b[n];
        const float* w = pg_w + n * CONDN;
#pragma unroll
        for (int k = 0; k < CONDN; k++) m += w[k] * c2[k];
        int o = n >> 6, c = n & 63;
        g_pw[b * (OCH * CH) + c * OCH + o] = fmaxf(m, 0.f);
    }
    for (int n = tid; n < OCH; n += 128) {
        float m = bg_b[n];
        const float* w = bg_w + n * CONDN;
#pragma unroll
        for (int k = 0; k < CONDN; k++) m += w[k] * c2[k];
        g_db[b * OCH + n] = m;
    }
}

// =============================================================================
// K3: fused depthwise 3x3 + pointwise + dynamic bias + fused BN partial stats.
//  - gridDim (2, 32, 32): (output-half, tile, batch). Half-pairs adjacent ->
//    shared x tile hits L2. 32 output channels per CTA -> ~110 regs -> 2 CTA/SM.
//  - 16x32 spatial tile, 2 adjacent pixels per thread (256 threads)
//  - depthwise y computed as f32x2 pixel-pair (9 FFMA2)
//  - cp.async double-buffered staging, all smem reads vectorized
// =============================================================================
#define CC8   8
#define XROW  36    // padded halo row width (34 used)

__device__ __forceinline__ void ffma2(ull& a, ull y, ull p) {
    asm("fma.rn.f32x2 %0, %1, %2, %0;" : "+l"(a) : "l"(y), "l"(p));
}
__device__ __forceinline__ ull mul2(ull a, ull b) {
    ull r; asm("mul.rn.f32x2 %0, %1, %2;" : "=l"(r) : "l"(a), "l"(b)); return r;
}
__device__ __forceinline__ ull dup2(float v) {
    ull r; asm("mov.b64 %0, {%1, %1};" : "=l"(r) : "r"(__float_as_uint(v)));
    return r;
}
__device__ __forceinline__ ull pack2(float lo, float hi) {
    ull r;
    asm("mov.b64 %0, {%1, %2};" : "=l"(r) : "r"(__float_as_uint(lo)), "r"(__float_as_uint(hi)));
    return r;
}
__device__ __forceinline__ void unpk(ull v, float& lo, float& hi) {
    unsigned a, b;
    asm("mov.b64 {%0, %1}, %2;" : "=r"(a), "=r"(b) : "l"(v));
    lo = __uint_as_float(a); hi = __uint_as_float(b);
}

__global__ void __launch_bounds__(256, 2)
k_main(const float* __restrict__ x, float* __restrict__ out) {
    __shared__ __align__(16) float xs[2][CC8 * 18 * XROW];   // 2 x 20736 B
    __shared__ __align__(16) float pwsh[2][CC8 * 32];        // 2 x 1024 B
    __shared__ __align__(16) float dwsh[CH * 12];            // padded 12/channel
    __shared__ float dbsh[32];
    __shared__ float red[8][64];

    const int h    = blockIdx.x;                 // output half 0/1
    const int tile = blockIdx.y;                 // 0..31
    const int b    = blockIdx.z;
    const int col0 = (tile & 3) * 32;
    const int row0 = (tile >> 2) * 16;
    const int tid  = threadIdx.x;                // 256
    const int tx   = tid & 15, ty = tid >> 4;

    for (int i = tid; i < CH * KK; i += 256)
        dwsh[(i / 9) * 12 + (i % 9)] = g_dw[b * CH * KK + i];
    if (tid < 32) dbsh[tid] = g_db[b * OCH + h * 32 + tid];

    auto stage = [&](int cc, int buf) {
        unsigned xsb = (unsigned)__cvta_generic_to_shared(&xs[buf][0]);
        for (int idx = tid; idx < CC8 * 18 * 34; idx += 256) {
            int c   = idx / (18 * 34);
            int rem = idx - c * (18 * 34);
            int row = rem / 34;
            int col = rem - row * 34;
            int gy = row0 - 1 + row;
            int gx = col0 - 1 + col;
            bool ok = (gy >= 0) & (gy < HW) & (gx >= 0) & (gx < HW);
            const float* gp = x + ((size_t)(b * CH + cc * CC8 + c) * NPIX
                                   + (ok ? (gy * HW + gx) : 0));
            unsigned dst = xsb + (unsigned)(((c * 18 + row) * XROW + col) * 4);
            int sz = ok ? 4 : 0;
            asm volatile("cp.async.ca.shared.global [%0], [%1], 4, %2;\n"
                         :: "r"(dst), "l"(gp), "r"(sz) : "memory");
        }
        // pw chunk for this half: 8ch x 32out = 64 x 16B
        if (tid < 64) {
            int c = tid >> 3, seg = tid & 7;
            const float* src = g_pw + (size_t)b * CH * OCH
                             + (cc * CC8 + c) * OCH + h * 32 + seg * 4;
            unsigned dst = (unsigned)__cvta_generic_to_shared(&pwsh[buf][0])
                         + (unsigned)((c * 32 + seg * 4) * 4);
            asm volatile("cp.async.cg.shared.global [%0], [%1], 16;\n"
                         :: "r"(dst), "l"(src) : "memory");
        }
    };

    stage(0, 0);
    asm volatile("cp.async.commit_group;\n" ::: "memory");

    ull acc0[16], acc1[16];   // 16 f32x2 out pairs, pixel0 / pixel1

    for (int cc = 0; cc < CH / CC8; cc++) {
        const int buf = cc & 1;
        if (cc < CH / CC8 - 1) {
            stage(cc + 1, buf ^ 1);
            asm volatile("cp.async.commit_group;\n" ::: "memory");
            asm volatile("cp.async.wait_group 1;\n" ::: "memory");
        } else {
            asm volatile("cp.async.wait_group 0;\n" ::: "memory");
        }
        __syncthreads();

        if (cc == 0) {
#pragma unroll
            for (int k = 0; k < 16; k++) {
                ull d = pack2(dbsh[2 * k], dbsh[2 * k + 1]);
                acc0[k] = d;
                acc1[k] = d;
            }
        }

        const float* xcbase = &xs[buf][0] + ty * XROW + 2 * tx;
#pragma unroll
        for (int c = 0; c < CC8; c++) {
            const float* xc = xcbase + c * 18 * XROW;
            const float* w  = &dwsh[(cc * CC8 + c) * 12];
            float4 w0 = *(const float4*)(w);
            float4 w1 = *(const float4*)(w + 4);
            float  w8 = w[8];

            // pixel-pair depthwise conv in f32x2 (9 FFMA2)
            ull yp;
            {
                ull A0 = *(const ull*)(xc);
                ull A1 = *(const ull*)(xc + 2);
                float alo, ahi, blo, bhi;
                unpk(A0, alo, ahi); unpk(A1, blo, bhi);
                ull M = pack2(ahi, blo);
                yp = mul2(A0, dup2(w0.x));
                ffma2(yp, M, dup2(w0.y));
                ffma2(yp, A1, dup2(w0.z));
            }
            {
                ull A0 = *(const ull*)(xc + XROW);
                ull A1 = *(const ull*)(xc + XROW + 2);
                float alo, ahi, blo, bhi;
                unpk(A0, alo, ahi); unpk(A1, blo, bhi);
                ull M = pack2(ahi, blo);
                ffma2(yp, A0, dup2(w0.w));
                ffma2(yp, M, dup2(w1.x));
                ffma2(yp, A1, dup2(w1.y));
            }
            {
                ull A0 = *(const ull*)(xc + 2 * XROW);
                ull A1 = *(const ull*)(xc + 2 * XROW + 2);
                float alo, ahi, blo, bhi;
                unpk(A0, alo, ahi); unpk(A1, blo, bhi);
                ull M = pack2(ahi, blo);
                ffma2(yp, A0, dup2(w1.z));
                ffma2(yp, M, dup2(w1.w));
                ffma2(yp, A1, dup2(w8));
            }
            float y0, y1;
            unpk(yp, y0, y1);
            ull yy0 = dup2(y0);
            ull yy1 = dup2(y1);

            const ulonglong2* pw2 = (const ulonglong2*)&pwsh[buf][c * 32];
#pragma unroll
            for (int j = 0; j < 8; j++) {
                ulonglong2 q = pw2[j];
                ffma2(acc0[2 * j],     yy0, q.x);
                ffma2(acc0[2 * j + 1], yy0, q.y);
                ffma2(acc1[2 * j],     yy1, q.x);
                ffma2(acc1[2 * j + 1], yy1, q.y);
            }
        }
        __syncthreads();
    }

    // ---- store: 2 adjacent pixels -> STG.64 per output channel ----
    const int gy = row0 + ty;
    const int gx = col0 + 2 * tx;
    float* op = out + (size_t)(b * OCH + h * 32) * NPIX + gy * HW + gx;
#pragma unroll
    for (int k = 0; k < 16; k++) {
        float p0l, p0h, p1l, p1h;
        unpk(acc0[k], p0l, p0h);
        unpk(acc1[k], p1l, p1h);
        *(float2*)(op + (size_t)(2 * k) * NPIX)     = make_float2(p0l, p1l);
        *(float2*)(op + (size_t)(2 * k + 1) * NPIX) = make_float2(p0h, p1h);
    }

    // ---- fused BN partial stats: per-block (32ch x {sum, sumsq}) ----
    const int lane = tid & 31, wp = tid >> 5;
#pragma unroll
    for (int k = 0; k < 16; k++) {
        float p0l, p0h, p1l, p1h;
        unpk(acc0[k], p0l, p0h);
        unpk(acc1[k], p1l, p1h);
        float s0 = p0l + p1l, q0 = p0l * p0l + p1l * p1l;
        float s1 = p0h + p1h, q1 = p0h * p0h + p1h * p1h;
#pragma unroll
        for (int off = 16; off > 0; off >>= 1) {
            s0 += __shfl_xor_sync(0xffffffffu, s0, off);
            q0 += __shfl_xor_sync(0xffffffffu, q0, off);
            s1 += __shfl_xor_sync(0xffffffffu, s1, off);
            q1 += __shfl_xor_sync(0xffffffffu, q1, off);
        }
        if (lane == 0) {
            red[wp][4 * k]     = s0;
            red[wp][4 * k + 1] = q0;
            red[wp][4 * k + 2] = s1;
            red[wp][4 * k + 3] = q1;
        }
    }
    __syncthreads();
    if (tid < 64) {
        float t = 0.f;
#pragma unroll
        for (int w2 = 0; w2 < 8; w2++) t += red[w2][tid];
        int bid = (b * 32 + tile) * 2 + h;
        g_part[bid * 64 + tid] = t;
    }
}

// =============================================================================
// K5: fold per-block partials -> per-channel scale/shift (one block per channel)
// =============================================================================
__global__ void k_finalize(const float* __restrict__ gamma,
                           const float* __restrict__ beta) {
    int o = blockIdx.x;                 // 0..63
    int h = o >> 5, loc = o & 31;
    int js = ((loc >> 1) << 2) + ((loc & 1) << 1);
    int tid = threadIdx.x;              // 256
    float S = 0.f, Q = 0.f;
    for (int m = tid; m < 1024; m += 256) {
        int bid = 2 * m + h;
        S += g_part[bid * 64 + js];
        Q += g_part[bid * 64 + js + 1];
    }
#pragma unroll
    for (int off = 16; off > 0; off >>= 1) {
        S += __shfl_xor_sync(0xffffffffu, S, off);
        Q += __shfl_xor_sync(0xffffffffu, Q, off);
    }
    __shared__ float ss[8], qq[8];
    int lane = tid & 31, w = tid >> 5;
    if (lane == 0) { ss[w] = S; qq[w] = Q; }
    __syncthreads();
    if (tid == 0) {
        float Sa = 0.f, Qa = 0.f;
#pragma unroll
        for (int w2 = 0; w2 < 8; w2++) { Sa += ss[w2]; Qa += qq[w2]; }
        const float inv = 1.0f / (float)(BATCH * NPIX);
        float mean = Sa * inv;
        float var  = Qa * inv - mean * mean;
        float sc = gamma[o] * rsqrtf(var + 1e-5f);
        g_scale[o] = sc;
        g_shift[o] = beta[o] - mean * sc;
    }
}

// =============================================================================
// K6: in-place normalize
// =============================================================================
__global__ void k_norm(float* __restrict__ out) {
    int plane = blockIdx.x;
    int o = plane & 63;
    float sc = g_scale[o], sh = g_shift[o];
    float4* p = reinterpret_cast<float4*>(out + (size_t)plane * NPIX);
    int tid = threadIdx.x;   // 256
    for (int i = tid; i < NPIX / 4; i += 256) {
        float4 v = p[i];
        v.x = v.x * sc + sh;
        v.y = v.y * sc + sh;
        v.z = v.z * sc + sh;
        v.w = v.w * sc + sh;
        p[i] = v;
    }
}

// =============================================================================
extern "C" void kernel_launch(void* const* d_in, const int* in_sizes, int n_in,
                              void* d_out, int out_size) {
    const float* x      = (const float*)d_in[0];
    const float* cg_w1  = (const float*)d_in[1];
    const float* cg_b1  = (const float*)d_in[2];
    const float* cg_w2  = (const float*)d_in[3];
    const float* cg_b2  = (const float*)d_in[4];
    const float* wg_w   = (const float*)d_in[5];
    const float* wg_b   = (const float*)d_in[6];
    const float* pg_w   = (const float*)d_in[7];
    const float* pg_b   = (const float*)d_in[8];
    const float* bg_w   = (const float*)d_in[9];
    const float* bg_b   = (const float*)d_in[10];
    const float* bn_g   = (const float*)d_in[11];
    const float* bn_b   = (const float*)d_in[12];
    float* out = (float*)d_out;

    k_ssum<<<BATCH * CH, 256>>>(x);
    k_cond<<<BATCH, 128>>>(cg_w1, cg_b1, cg_w2, cg_b2,
                           wg_w, wg_b, pg_w, pg_b, bg_w, bg_b);
    dim3 g3(2, 32, BATCH);
    k_main<<<g3, 256>>>(x, out);
    k_finalize<<<OCH, 256>>>(bn_g, bn_b);
    k_norm<<<BATCH * OCH, 256>>>(out);
}

// round 14
// speedup vs baseline: 1.0946x; 1.0946x over previous
#include <cuda_runtime.h>
#include <cstdint>

#define BATCH 32
#define CH    64
#define OCH   64
#define HW    128
#define NPIX  16384
#define CONDN 16
#define KK    9

typedef unsigned long long ull;

// ---------------- scratch (device globals; no allocation allowed) -------------
__device__ float g_S[BATCH * CH * KK];        // strided sums  [b][c][i*3+j]
__device__ float g_dw[BATCH * CH * KK];       // depthwise weights
__device__ float g_pw[BATCH * CH * OCH];      // pointwise, stored [b][c][o]
__device__ float g_db[BATCH * OCH];           // dynamic bias
__device__ float g_part[1024 * 128];          // per-block BN partials
__device__ float g_scale[OCH];
__device__ float g_shift[OCH];

// =============================================================================
// K1: strided partial sums S[b,c,i,j] = sum_{p,q=0..62} x[b,c,2p+i,2q+j]
// =============================================================================
__global__ void k_ssum(const float* __restrict__ x) {
    int bc = blockIdx.x;                       // b*64 + c
    const float* xp = x + (size_t)bc * NPIX;
    int tid = threadIdx.x;                     // 256
    int s = tid & 127;
    int rbase = tid >> 7;

    float a[9];
#pragma unroll
    for (int m = 0; m < 9; m++) a[m] = 0.f;

    bool se = (s & 1) == 0;
    bool j0 = se && (s <= 124);
    bool j1 = (!se) && (s <= 125);
    bool j2 = se && (s >= 2);

    for (int k = 0; k < 64; k++) {
        int r = rbase + 2 * k;
        float v = xp[r * HW + s];
        bool re = (r & 1) == 0;
        bool i0 = re && (r <= 124);
        bool i1 = (!re) && (r <= 125);
        bool i2 = re && (r >= 2);
        if (i0) { if (j0) a[0] += v; if (j1) a[1] += v; if (j2) a[2] += v; }
        if (i1) { if (j0) a[3] += v; if (j1) a[4] += v; if (j2) a[5] += v; }
        if (i2) { if (j0) a[6] += v; if (j1) a[7] += v; if (j2) a[8] += v; }
    }

#pragma unroll
    for (int m = 0; m < 9; m++)
#pragma unroll
        for (int off = 16; off > 0; off >>= 1)
            a[m] += __shfl_xor_sync(0xffffffffu, a[m], off);

    __shared__ float red[8][9];
    int lane = tid & 31, w = tid >> 5;
    if (lane == 0) {
#pragma unroll
        for (int m = 0; m < 9; m++) red[w][m] = a[m];
    }
    __syncthreads();
    if (tid < 9) {
        float t = 0.f;
#pragma unroll
        for (int w2 = 0; w2 < 8; w2++) t += red[w2][tid];
        g_S[bc * 9 + tid] = t;
    }
}

// =============================================================================
// K2: conditioning network + dynamic weight generators (one block per sample)
// =============================================================================
__global__ void k_cond(const float* __restrict__ cg_w1, const float* __restrict__ cg_b1,
                       const float* __restrict__ cg_w2, const float* __restrict__ cg_b2,
                       const float* __restrict__ wg_w,  const float* __restrict__ wg_b,
                       const float* __restrict__ pg_w,  const float* __restrict__ pg_b,
                       const float* __restrict__ bg_w,  const float* __restrict__ bg_b) {
    int b = blockIdx.x;
    int tid = threadIdx.x;   // 128
    __shared__ float Ssh[CH * KK];
    __shared__ float c1[CONDN];
    __shared__ float c2[CONDN];

    for (int i = tid; i < CH * KK; i += 128) Ssh[i] = g_S[b * (CH * KK) + i];
    __syncthreads();

    if (tid < CONDN) {
        float m = 0.f;
        const float* w = cg_w1 + tid * (CH * KK);
        for (int i = 0; i < CH * KK; i++) m += w[i] * Ssh[i];
        m = m * (1.0f / 3969.0f) + cg_b1[tid];
        c1[tid] = fmaxf(m, 0.f);
    }
    __syncthreads();
    if (tid < CONDN) {
        float m = cg_b2[tid];
#pragma unroll
        for (int k = 0; k < CONDN; k++) m += cg_w2[tid * CONDN + k] * c1[k];
        c2[tid] = fmaxf(m, 0.f);
    }
    __syncthreads();

    for (int n = tid; n < CH * KK; n += 128) {
        float m = wg_b[n];
        const float* w = wg_w + n * CONDN;
#pragma unroll
        for (int k = 0; k < CONDN; k++) m += w[k] * c2[k];
        g_dw[b * (CH * KK) + n] = fmaxf(m, 0.f);
    }
    for (int n = tid; n < OCH * CH; n += 128) {
        float m = pg_b[n];
        const float* w = pg_w + n * CONDN;
#pragma unroll
        for (int k = 0; k < CONDN; k++) m += w[k] * c2[k];
        int o = n >> 6, c = n & 63;
        g_pw[b * (OCH * CH) + c * OCH + o] = fmaxf(m, 0.f);
    }
    for (int n = tid; n < OCH; n += 128) {
        float m = bg_b[n];
        const float* w = bg_w + n * CONDN;
#pragma unroll
        for (int k = 0; k < CONDN; k++) m += w[k] * c2[k];
        g_db[b * OCH + n] = m;
    }
}

// =============================================================================
// K3: fused depthwise 3x3 + pointwise 1x1 + dynamic bias + BN partial stats.
//  - 16x32 spatial tile, 2 adjacent pixels per thread, 64 outputs per CTA
//  - 16 chunks of 4 input channels, cp.async double-buffered
//  - staging: 8x16B + 2x4B per halo row (16B-aligned layout, XROW=40)
//  - depthwise in f32x2 (9 FFMA2), pre-packed dw pairs; pointwise 64 FFMA2/ch
//  - epilogue writes out + per-block BN sum/sumsq partials (k_stats deleted)
// =============================================================================
#define CC4   4
#define XROW  40    // j in [-4..35] conceptually; used idx 2..37; s(j)=j+4

__device__ __forceinline__ void ffma2(ull& a, ull y, ull p) {
    asm("fma.rn.f32x2 %0, %1, %2, %0;" : "+l"(a) : "l"(y), "l"(p));
}
__device__ __forceinline__ ull mul2(ull a, ull b) {
    ull r; asm("mul.rn.f32x2 %0, %1, %2;" : "=l"(r) : "l"(a), "l"(b)); return r;
}
__device__ __forceinline__ ull dup2(float v) {
    ull r; asm("mov.b64 %0, {%1, %1};" : "=l"(r) : "r"(__float_as_uint(v)));
    return r;
}
__device__ __forceinline__ ull pack2(float lo, float hi) {
    ull r;
    asm("mov.b64 %0, {%1, %2};" : "=l"(r) : "r"(__float_as_uint(lo)), "r"(__float_as_uint(hi)));
    return r;
}
__device__ __forceinline__ void unpk(ull v, float& lo, float& hi) {
    unsigned a, b;
    asm("mov.b64 {%0, %1}, %2;" : "=r"(a), "=r"(b) : "l"(v));
    lo = __uint_as_float(a); hi = __uint_as_float(b);
}

__global__ void __launch_bounds__(256, 1)
k_main(const float* __restrict__ x, float* __restrict__ out) {
    __shared__ __align__(16) float xs[2][CC4 * 18 * XROW];   // 2 x 11520 B
    __shared__ __align__(16) float pwsh[2][CC4 * OCH];       // 2 x 1024 B
    __shared__ __align__(16) ull   dwsh2[CH * KK];           // packed pairs, 4608 B
    __shared__ float dbsh[OCH];
    __shared__ float red[8][128];                            // 4096 B

    const int tile = blockIdx.x;                 // 0..31
    const int b    = blockIdx.y;
    const int col0 = (tile & 3) * 32;
    const int row0 = (tile >> 2) * 16;
    const int tid  = threadIdx.x;                // 256
    const int tx   = tid & 15, ty = tid >> 4;

    for (int i = tid; i < CH * KK; i += 256) {
        float v = g_dw[b * CH * KK + i];
        dwsh2[i] = pack2(v, v);
    }
    if (tid < OCH) dbsh[tid] = g_db[b * OCH + tid];

    auto stage = [&](int cc, int buf) {
        unsigned xsb = (unsigned)__cvta_generic_to_shared(&xs[buf][0]);
        const float* xbase = x + (size_t)(b * CH + cc * CC4) * NPIX;
        // 4 channels x 18 rows x (8x16B interior + 2x4B edges) = 720 ops
        for (int idx = tid; idx < CC4 * 18 * 10; idx += 256) {
            int c   = idx / 180;
            int rem = idx - c * 180;
            int row = rem / 10;
            int op  = rem - row * 10;
            int gy  = row0 - 1 + row;
            bool gyok = ((unsigned)gy < 128u);
            int gyc = gyok ? gy : 0;
            const float* srow = xbase + (size_t)c * NPIX + gyc * HW;
            unsigned drow = xsb + (unsigned)(((c * 18 + row) * XROW) * 4);
            if (op < 8) {
                // interior 16B: j = 4*op .. 4*op+3  (gx = col0+4*op, aligned)
                const float* src = srow + col0 + 4 * op;
                unsigned dst = drow + (unsigned)((4 + 4 * op) * 4);
                int sz = gyok ? 16 : 0;
                asm volatile("cp.async.ca.shared.global [%0], [%1], 16, %2;\n"
                             :: "r"(dst), "l"(src), "r"(sz) : "memory");
            } else if (op == 8) {
                // left edge j=-1 (idx 3)
                bool ok = gyok && (col0 > 0);
                const float* src = srow + (ok ? (col0 - 1) : 0);
                unsigned dst = drow + 3 * 4;
                int sz = ok ? 4 : 0;
                asm volatile("cp.async.ca.shared.global [%0], [%1], 4, %2;\n"
                             :: "r"(dst), "l"(src), "r"(sz) : "memory");
            } else {
                // right edge j=32 (idx 36)
                bool ok = gyok && (col0 < 96);
                const float* src = srow + (ok ? (col0 + 32) : 0);
                unsigned dst = drow + 36 * 4;
                int sz = ok ? 4 : 0;
                asm volatile("cp.async.ca.shared.global [%0], [%1], 4, %2;\n"
                             :: "r"(dst), "l"(src), "r"(sz) : "memory");
            }
        }
        // pw chunk: 4ch x 64 outs = 256 floats = 64 x 16B
        if (tid < 64) {
            const float* src = g_pw + (size_t)b * CH * OCH + cc * CC4 * OCH + tid * 4;
            unsigned dst = (unsigned)__cvta_generic_to_shared(&pwsh[buf][0]) + tid * 16;
            asm volatile("cp.async.cg.shared.global [%0], [%1], 16;\n"
                         :: "r"(dst), "l"(src) : "memory");
        }
    };

    stage(0, 0);
    asm volatile("cp.async.commit_group;\n" ::: "memory");

    ull acc0[32], acc1[32];   // 32 output pairs, pixel0 / pixel1

    for (int cc = 0; cc < CH / CC4; cc++) {
        const int buf = cc & 1;
        if (cc < CH / CC4 - 1) {
            stage(cc + 1, buf ^ 1);
            asm volatile("cp.async.commit_group;\n" ::: "memory");
            asm volatile("cp.async.wait_group 1;\n" ::: "memory");
        } else {
            asm volatile("cp.async.wait_group 0;\n" ::: "memory");
        }
        __syncthreads();

        if (cc == 0) {
#pragma unroll
            for (int k = 0; k < 32; k++) {
                ull d = pack2(dbsh[2 * k], dbsh[2 * k + 1]);
                acc0[k] = d;
                acc1[k] = d;
            }
        }

        // base tap index: row ty, first load covers j = 2tx-2, 2tx-1
        const float* xcb = &xs[buf][0] + ty * XROW + 2 * tx + 2;
#pragma unroll
        for (int c = 0; c < CC4; c++) {
            const float* xc  = xcb + c * 18 * XROW;
            const ull*  dwp = &dwsh2[(cc * CC4 + c) * KK];

            ull yp;
            {   // row 0
                ull L = *(const ull*)(xc);
                ull C = *(const ull*)(xc + 2);
                ull R = *(const ull*)(xc + 4);
                float llo, lhi, clo, chi, rlo, rhi;
                unpk(L, llo, lhi); unpk(C, clo, chi); unpk(R, rlo, rhi);
                yp = mul2(pack2(lhi, clo), dwp[0]);
                ffma2(yp, C, dwp[1]);
                ffma2(yp, pack2(chi, rlo), dwp[2]);
            }
            {   // row 1
                ull L = *(const ull*)(xc + XROW);
                ull C = *(const ull*)(xc + XROW + 2);
                ull R = *(const ull*)(xc + XROW + 4);
                float llo, lhi, clo, chi, rlo, rhi;
                unpk(L, llo, lhi); unpk(C, clo, chi); unpk(R, rlo, rhi);
                ffma2(yp, pack2(lhi, clo), dwp[3]);
                ffma2(yp, C, dwp[4]);
                ffma2(yp, pack2(chi, rlo), dwp[5]);
            }
            {   // row 2
                ull L = *(const ull*)(xc + 2 * XROW);
                ull C = *(const ull*)(xc + 2 * XROW + 2);
                ull R = *(const ull*)(xc + 2 * XROW + 4);
                float llo, lhi, clo, chi, rlo, rhi;
                unpk(L, llo, lhi); unpk(C, clo, chi); unpk(R, rlo, rhi);
                ffma2(yp, pack2(lhi, clo), dwp[6]);
                ffma2(yp, C, dwp[7]);
                ffma2(yp, pack2(chi, rlo), dwp[8]);
            }
            float y0, y1;
            unpk(yp, y0, y1);
            ull yy0 = dup2(y0);
            ull yy1 = dup2(y1);

            const ulonglong2* pw2 = (const ulonglong2*)&pwsh[buf][c * OCH];
#pragma unroll
            for (int j = 0; j < 16; j++) {
                ulonglong2 q = pw2[j];
                ffma2(acc0[2 * j],     yy0, q.x);
                ffma2(acc0[2 * j + 1], yy0, q.y);
                ffma2(acc1[2 * j],     yy1, q.x);
                ffma2(acc1[2 * j + 1], yy1, q.y);
            }
        }
        __syncthreads();
    }

    // ---- store: 2 adjacent pixels -> STG.64 per output channel ----
    const int gy = row0 + ty;
    const int gx = col0 + 2 * tx;
    float* op = out + (size_t)(b * OCH) * NPIX + gy * HW + gx;
#pragma unroll
    for (int k = 0; k < 32; k++) {
        float p0l, p0h, p1l, p1h;
        unpk(acc0[k], p0l, p0h);
        unpk(acc1[k], p1l, p1h);
        *(float2*)(op + (size_t)(2 * k) * NPIX)     = make_float2(p0l, p1l);
        *(float2*)(op + (size_t)(2 * k + 1) * NPIX) = make_float2(p0h, p1h);
    }

    // ---- fused BN partial stats: per-block (64ch x {sum, sumsq}) ----
    const int lane = tid & 31, wp = tid >> 5;
#pragma unroll
    for (int k = 0; k < 32; k++) {
        float p0l, p0h, p1l, p1h;
        unpk(acc0[k], p0l, p0h);
        unpk(acc1[k], p1l, p1h);
        float s0 = p0l + p1l, q0 = p0l * p0l + p1l * p1l;   // channel 2k
        float s1 = p0h + p1h, q1 = p0h * p0h + p1h * p1h;   // channel 2k+1
#pragma unroll
        for (int off = 16; off > 0; off >>= 1) {
            s0 += __shfl_xor_sync(0xffffffffu, s0, off);
            q0 += __shfl_xor_sync(0xffffffffu, q0, off);
            s1 += __shfl_xor_sync(0xffffffffu, s1, off);
            q1 += __shfl_xor_sync(0xffffffffu, q1, off);
        }
        if (lane == 0) {
            red[wp][4 * k]     = s0;
            red[wp][4 * k + 1] = q0;
            red[wp][4 * k + 2] = s1;
            red[wp][4 * k + 3] = q1;
        }
    }
    __syncthreads();
    if (tid < 128) {
        float t = 0.f;
#pragma unroll
        for (int w2 = 0; w2 < 8; w2++) t += red[w2][tid];
        int bid = b * 32 + tile;
        g_part[bid * 128 + tid] = t;
    }
}

// =============================================================================
// K5: fold per-block partials -> per-channel scale/shift (one block per channel)
// =============================================================================
__global__ void k_finalize(const float* __restrict__ gamma,
                           const float* __restrict__ beta) {
    int o = blockIdx.x;                 // 0..63
    int j = 4 * (o >> 1) + 2 * (o & 1); // s index; q at j+1
    int tid = threadIdx.x;              // 256
    float S = 0.f, Q = 0.f;
    for (int m = tid; m < 1024; m += 256) {
        S += g_part[m * 128 + j];
        Q += g_part[m * 128 + j + 1];
    }
#pragma unroll
    for (int off = 16; off > 0; off >>= 1) {
        S += __shfl_xor_sync(0xffffffffu, S, off);
        Q += __shfl_xor_sync(0xffffffffu, Q, off);
    }
    __shared__ float ss[8], qq[8];
    int lane = tid & 31, w = tid >> 5;
    if (lane == 0) { ss[w] = S; qq[w] = Q; }
    __syncthreads();
    if (tid == 0) {
        float Sa = 0.f, Qa = 0.f;
#pragma unroll
        for (int w2 = 0; w2 < 8; w2++) { Sa += ss[w2]; Qa += qq[w2]; }
        const float inv = 1.0f / (float)(BATCH * NPIX);
        float mean = Sa * inv;
        float var  = Qa * inv - mean * mean;
        float sc = gamma[o] * rsqrtf(var + 1e-5f);
        g_scale[o] = sc;
        g_shift[o] = beta[o] - mean * sc;
    }
}

// =============================================================================
// K6: in-place normalize
// =============================================================================
__global__ void k_norm(float* __restrict__ out) {
    int plane = blockIdx.x;
    int o = plane & 63;
    float sc = g_scale[o], sh = g_shift[o];
    float4* p = reinterpret_cast<float4*>(out + (size_t)plane * NPIX);
    int tid = threadIdx.x;   // 256
    for (int i = tid; i < NPIX / 4; i += 256) {
        float4 v = p[i];
        v.x = v.x * sc + sh;
        v.y = v.y * sc + sh;
        v.z = v.z * sc + sh;
        v.w = v.w * sc + sh;
        p[i] = v;
    }
}

// =============================================================================
extern "C" void kernel_launch(void* const* d_in, const int* in_sizes, int n_in,
                              void* d_out, int out_size) {
    const float* x      = (const float*)d_in[0];
    const float* cg_w1  = (const float*)d_in[1];
    const float* cg_b1  = (const float*)d_in[2];
    const float* cg_w2  = (const float*)d_in[3];
    const float* cg_b2  = (const float*)d_in[4];
    const float* wg_w   = (const float*)d_in[5];
    const float* wg_b   = (const float*)d_in[6];
    const float* pg_w   = (const float*)d_in[7];
    const float* pg_b   = (const float*)d_in[8];
    const float* bg_w   = (const float*)d_in[9];
    const float* bg_b   = (const float*)d_in[10];
    const float* bn_g   = (const float*)d_in[11];
    const float* bn_b   = (const float*)d_in[12];
    float* out = (float*)d_out;

    k_ssum<<<BATCH * CH, 256>>>(x);
    k_cond<<<BATCH, 128>>>(cg_w1, cg_b1, cg_w2, cg_b2,
                           wg_w, wg_b, pg_w, pg_b, bg_w, bg_b);
    dim3 g3(32, BATCH);
    k_main<<<g3, 256>>>(x, out);
    k_finalize<<<OCH, 256>>>(bn_g, bn_b);
    k_norm<<<BATCH * OCH, 256>>>(out);
}